// round 14
// baseline (speedup 1.0000x reference)
#include <cuda_runtime.h>
#include <cuda_bf16.h>
#include <math.h>
#include <stdint.h>

#define BT    4096
#define HID   256
#define TSTEP 64
#define BB    64
#define NCTA  128

// ---------------- scratch (static device memory; no allocations) ----------------
__device__ float g_feat  [BT * HID];          // conv features (B*T, 256)
__device__ float g_gatesx[BT * 1024];         // x @ Wk + b, TRANSPOSED: [t][gatecol][b]
__device__ float g_lstm  [BT * HID];          // lstm hidden states
__device__ float g_Wr4   [256 * 1024];        // Wr packed: [k][j][gate] interleaved
__device__ float g_hbuf  [2][16384];          // LSTM h double buffer, [j][b]
__device__ float g_pimlog[16777216];          // pim logits (4096 x 4096)
__device__ uint2 g_Asp   [128 * 4096];        // split activations [kpair][m] (hi-pair, lo-pair)
__device__ uint2 g_Bpim  [128 * 4096];        // split pim_W [kpair][n]
__device__ uint2 g_Bk    [128 * 1024];        // split lstm_k [kpair][n]
__device__ float g_pir   [BT * 36];           // pir probabilities
__device__ float g_entpir[BT];
__device__ float g_entpim[BT];
__device__ float g_ppim  [BT];                // pim prob of taken action
__device__ float g_vpred [BT];
__device__ float g_pgvals[BT];
__device__ float g_vfvals[BT];
__device__ float g_stats [2];                 // gae mean, std
__device__ unsigned g_bar_cnt = 0;            // grid barrier arrive counter
__device__ unsigned g_bar_phase = 0;          // grid barrier phase flag

__device__ __forceinline__ float leaky(float v) { return v > 0.f ? v : 0.2f * v; }
__device__ __forceinline__ float sigmoidf(float v) { return 1.f / (1.f + expf(-v)); }

__device__ __forceinline__ uint32_t smem_u32(const void* p)
{
    uint32_t a;
    asm("{ .reg .u64 t; cvta.to.shared.u64 t, %1; cvt.u32.u64 %0, t; }" : "=r"(a) : "l"(p));
    return a;
}

__device__ __forceinline__ void cp_async16(uint32_t dst, const void* src)
{
    asm volatile("cp.async.cg.shared.global [%0], [%1], 16;" :: "r"(dst), "l"(src));
}

// ---------------- fused conv stack: one block per image ----------------
__global__ __launch_bounds__(128) void conv_kernel(
    const float* __restrict__ x,
    const float* __restrict__ W1, const float* __restrict__ b1,
    const float* __restrict__ W2, const float* __restrict__ b2,
    const float* __restrict__ W3, const float* __restrict__ b3,
    const float* __restrict__ W4, const float* __restrict__ b4)
{
    __shared__ float sx[832];   // 13*8*8
    __shared__ float h1[384];   // 6*4*16
    __shared__ float h2[480];   // 5*3*32
    __shared__ float h3[128];   // 2*1*64
    const int img = blockIdx.x;
    const float* xin = x + img * 832;
    for (int i = threadIdx.x; i < 832; i += blockDim.x) sx[i] = xin[i];
    __syncthreads();

    // conv1: (13,8,8) -> (6,4,16), k=2 s=2
    for (int idx = threadIdx.x; idx < 384; idx += blockDim.x) {
        int oc = idx & 15, sp = idx >> 4;
        int ow = sp & 3, oh = sp >> 2;
        float v = b1[oc];
        #pragma unroll
        for (int kh = 0; kh < 2; kh++)
        #pragma unroll
        for (int kw = 0; kw < 2; kw++) {
            const float* xp = &sx[((oh * 2 + kh) * 8 + (ow * 2 + kw)) * 8];
            const float* wp = &W1[((kh * 2 + kw) * 8) * 16 + oc];
            #pragma unroll
            for (int ic = 0; ic < 8; ic++) v += xp[ic] * wp[ic * 16];
        }
        h1[idx] = leaky(v);
    }
    __syncthreads();

    // conv2: (6,4,16) -> (5,3,32), k=2 s=1
    for (int idx = threadIdx.x; idx < 480; idx += blockDim.x) {
        int oc = idx & 31, sp = idx >> 5;
        int ow = sp % 3, oh = sp / 3;
        float v = b2[oc];
        #pragma unroll
        for (int kh = 0; kh < 2; kh++)
        #pragma unroll
        for (int kw = 0; kw < 2; kw++) {
            const float* hp = &h1[((oh + kh) * 4 + (ow + kw)) * 16];
            const float* wp = &W2[((kh * 2 + kw) * 16) * 32 + oc];
            #pragma unroll
            for (int ic = 0; ic < 16; ic++) v += hp[ic] * wp[ic * 32];
        }
        h2[idx] = leaky(v);
    }
    __syncthreads();

    // conv3: (5,3,32) -> (2,1,64), k=2 s=2
    for (int idx = threadIdx.x; idx < 128; idx += blockDim.x) {
        int oc = idx & 63, oh = idx >> 6;
        float v = b3[oc];
        #pragma unroll
        for (int kh = 0; kh < 2; kh++)
        #pragma unroll
        for (int kw = 0; kw < 2; kw++) {
            const float* hp = &h2[((oh * 2 + kh) * 3 + kw) * 32];
            const float* wp = &W3[((kh * 2 + kw) * 32) * 64 + oc];
            #pragma unroll
            for (int ic = 0; ic < 32; ic++) v += hp[ic] * wp[ic * 64];
        }
        h3[idx] = leaky(v);
    }
    __syncthreads();

    // conv4 1x1: (2,1,64)->(2,1,128) + channels_first flatten: feat[2*oc+oh]
    for (int idx = threadIdx.x; idx < 256; idx += blockDim.x) {
        int oc = idx >> 1, oh = idx & 1;
        float v = b4[oc];
        #pragma unroll
        for (int ic = 0; ic < 64; ic++) v += h3[oh * 64 + ic] * W4[ic * 128 + oc];
        g_feat[img * 256 + idx] = leaky(v);
    }
}

// ---------------- bf16 hi/lo split helpers ----------------
__device__ __forceinline__ uint2 split_bf16pair(float a0, float a1)
{
    __nv_bfloat16 h0 = __float2bfloat16(a0);
    __nv_bfloat16 h1 = __float2bfloat16(a1);
    float r0 = a0 - __bfloat162float(h0);
    float r1 = a1 - __bfloat162float(h1);
    __nv_bfloat162 hp = __halves2bfloat162(h0, h1);
    __nv_bfloat162 lp = __halves2bfloat162(__float2bfloat16(r0), __float2bfloat16(r1));
    uint2 r;
    r.x = *(const uint32_t*)&hp;
    r.y = *(const uint32_t*)&lp;
    return r;
}

// split + transpose: src [4096][K] f32 -> dst [K/2][4096] uint2
__global__ __launch_bounds__(256) void split_tr4096_kernel(const float* __restrict__ src,
                                                           uint2* __restrict__ dst, int K)
{
    int idx = blockIdx.x * 256 + threadIdx.x;
    int kp = idx >> 12, m = idx & 4095;
    float2 a = *(const float2*)&src[(size_t)m * K + 2 * kp];
    dst[idx] = split_bf16pair(a.x, a.y);
}

// split B [K][N] f32 -> [K/2][N] uint2
__global__ __launch_bounds__(256) void splitB_kernel(const float* __restrict__ src,
                                                     uint2* __restrict__ dst, int N)
{
    int idx = blockIdx.x * 256 + threadIdx.x;
    int kp = idx / N, n = idx - kp * N;
    float a0 = src[(size_t)(2 * kp) * N + n];
    float a1 = src[(size_t)(2 * kp + 1) * N + n];
    dst[idx] = split_bf16pair(a0, a1);
}

// ---------------- 3xBF16 tensor GEMM (m16n8k16), pre-split inputs, cp.async ----------
#define MMA_BF16(d, a, b0v, b1v) \
    asm volatile("mma.sync.aligned.m16n8k16.row.col.f32.bf16.bf16.f32 " \
        "{%0,%1,%2,%3}, {%4,%5,%6,%7}, {%8,%9}, {%0,%1,%2,%3};" \
        : "+f"((d)[0]), "+f"((d)[1]), "+f"((d)[2]), "+f"((d)[3]) \
        : "r"((a)[0]), "r"((a)[1]), "r"((a)[2]), "r"((a)[3]), "r"(b0v), "r"(b1v))

#define PS_KP    16                   // kpairs per tile (K=32 per tile)
#define PS_TILE  (PS_KP * 132)        // uint2 per tile buffer
#define PS_SMEM_BYTES (4 * PS_TILE * 8)

__device__ __forceinline__ void load_tiles_ps(uint2* Asb, uint2* Bsb,
    const uint2* __restrict__ A, const uint2* __restrict__ B,
    int M, int N, int m0, int n0, int kp0, int tid)
{
    #pragma unroll
    for (int i = 0; i < 4; i++) {
        int r  = (tid >> 6) + (i << 2);      // kpair row 0..15
        int cc = (tid & 63) << 1;            // uint2 col 0..126
        cp_async16(smem_u32(Asb + r * 132 + cc), A + (size_t)(kp0 + r) * M + m0 + cc);
        cp_async16(smem_u32(Bsb + r * 132 + cc), B + (size_t)(kp0 + r) * N + n0 + cc);
    }
}

__global__ __launch_bounds__(256) void bf16_gemm_ps_kernel(
    const uint2* __restrict__ A, const uint2* __restrict__ B,
    const float* __restrict__ bias, float* __restrict__ C,
    int M, int N, int K2, int trans_out)
{
    extern __shared__ uint2 ps[];
    uint2* As0 = ps;
    uint2* Bs0 = ps + 2 * PS_TILE;
    const int tid  = threadIdx.x;
    const int lane = tid & 31, warp = tid >> 5;
    const int wm = warp & 3, wn = warp >> 2;
    const int g = lane >> 2, tg = lane & 3;
    const int m0 = blockIdx.y * 128, n0 = blockIdx.x * 128;

    float acc[2][8][4];
    #pragma unroll
    for (int a = 0; a < 2; a++)
        #pragma unroll
        for (int b = 0; b < 8; b++)
            #pragma unroll
            for (int c = 0; c < 4; c++) acc[a][b][c] = 0.f;

    load_tiles_ps(As0, Bs0, A, B, M, N, m0, n0, 0, tid);
    asm volatile("cp.async.commit_group;" ::: "memory");

    int st = 0;
    for (int kp0 = 0; kp0 < K2; kp0 += PS_KP) {
        if (kp0 + PS_KP < K2) {
            load_tiles_ps(As0 + (st ^ 1) * PS_TILE, Bs0 + (st ^ 1) * PS_TILE,
                          A, B, M, N, m0, n0, kp0 + PS_KP, tid);
            asm volatile("cp.async.commit_group;" ::: "memory");
            asm volatile("cp.async.wait_group 1;" ::: "memory");
        } else {
            asm volatile("cp.async.wait_group 0;" ::: "memory");
        }
        __syncthreads();

        const uint2* Ac = As0 + st * PS_TILE;
        const uint2* Bc = Bs0 + st * PS_TILE;

        #pragma unroll
        for (int kk = 0; kk < PS_KP; kk += 8) {
            uint32_t ah[2][4], al[2][4];
            #pragma unroll
            for (int mt = 0; mt < 2; mt++) {
                const int rb = wm * 32 + mt * 16;
                uint2 x0 = Ac[(kk + tg) * 132 + rb + g];
                uint2 x1 = Ac[(kk + tg) * 132 + rb + g + 8];
                uint2 x2 = Ac[(kk + tg + 4) * 132 + rb + g];
                uint2 x3 = Ac[(kk + tg + 4) * 132 + rb + g + 8];
                ah[mt][0] = x0.x; al[mt][0] = x0.y;
                ah[mt][1] = x1.x; al[mt][1] = x1.y;
                ah[mt][2] = x2.x; al[mt][2] = x2.y;
                ah[mt][3] = x3.x; al[mt][3] = x3.y;
            }
            #pragma unroll
            for (int nt = 0; nt < 8; nt++) {
                const int nb = wn * 64 + nt * 8 + g;
                uint2 y0 = Bc[(kk + tg) * 132 + nb];
                uint2 y1 = Bc[(kk + tg + 4) * 132 + nb];
                #pragma unroll
                for (int mt = 0; mt < 2; mt++) {
                    MMA_BF16(acc[mt][nt], ah[mt], y0.x, y1.x);  // hi*hi
                    MMA_BF16(acc[mt][nt], al[mt], y0.x, y1.x);  // lo*hi
                    MMA_BF16(acc[mt][nt], ah[mt], y0.y, y1.y);  // hi*lo
                }
            }
        }
        __syncthreads();
        st ^= 1;
    }

    #pragma unroll
    for (int mt = 0; mt < 2; mt++) {
        const int r0 = m0 + wm * 32 + mt * 16 + g;
        #pragma unroll
        for (int nt = 0; nt < 8; nt++) {
            const int col = n0 + wn * 64 + nt * 8 + 2 * tg;
            const float b0v = bias[col], b1v = bias[col + 1];
            if (!trans_out) {
                *(float2*)&C[(size_t)r0 * N + col] =
                    make_float2(acc[mt][nt][0] + b0v, acc[mt][nt][1] + b1v);
                *(float2*)&C[(size_t)(r0 + 8) * N + col] =
                    make_float2(acc[mt][nt][2] + b0v, acc[mt][nt][3] + b1v);
            } else {
                int t0 = r0 & 63, bb0 = r0 >> 6;
                int t1 = (r0 + 8) & 63, bb1 = (r0 + 8) >> 6;
                C[((size_t)t0 << 16) + ((size_t)col << 6) + bb0]       = acc[mt][nt][0] + b0v;
                C[((size_t)t0 << 16) + ((size_t)(col + 1) << 6) + bb0] = acc[mt][nt][1] + b1v;
                C[((size_t)t1 << 16) + ((size_t)col << 6) + bb1]       = acc[mt][nt][2] + b0v;
                C[((size_t)t1 << 16) + ((size_t)(col + 1) << 6) + bb1] = acc[mt][nt][3] + b1v;
            }
        }
    }
}

// ---------------- pack Wr: Wr[k*1024 + g*256 + j] -> g_Wr4[k*1024 + j*4 + g] ----------------
__global__ __launch_bounds__(256) void pack_wr_kernel(const float* __restrict__ Wr)
{
    int idx = blockIdx.x * 256 + threadIdx.x;
    int k = idx >> 10, col = idx & 1023;
    int g = col >> 8, j = col & 255;
    g_Wr4[(k << 10) + (j << 2) + g] = Wr[idx];
}

// ---------------- LSTM: persistent full-chip kernel, release/acquire grid barrier ----------
#define LSTM_SMEM_BYTES ((2048 + 16384 + 4096) * 4)

__device__ __forceinline__ void grid_barrier(unsigned target)
{
    __syncthreads();
    if (threadIdx.x == 0) {
        unsigned v;
        asm volatile("atom.add.release.gpu.u32 %0, [%1], 1;"
                     : "=r"(v) : "l"(&g_bar_cnt) : "memory");
        if (v == NCTA - 1) {
            g_bar_cnt = 0;
            asm volatile("st.release.gpu.u32 [%0], %1;"
                         :: "l"(&g_bar_phase), "r"(target) : "memory");
        } else {
            unsigned p;
            do {
                asm volatile("ld.acquire.gpu.u32 %0, [%1];"
                             : "=r"(p) : "l"(&g_bar_phase) : "memory");
            } while (p < target);
        }
    }
    __syncthreads();
}

__global__ __launch_bounds__(512) void lstm_persist_kernel()
{
    extern __shared__ float smem[];
    float*  sw  = smem;                       // [k*8 + c] weight slice, 2048 floats
    float*  sh  = smem + 2048;                // h tile [k*64 + b], 16384 floats
    float4* sp4 = (float4*)(smem + 2048 + 16384); // partials

    const int tid = threadIdx.x;
    const int row = tid & 63;
    const int oct = tid >> 6;
    const int jbase = blockIdx.x << 1;

    const float* wsrc = g_Wr4 + (jbase << 2);
    for (int i = tid; i < 2048; i += 512) {
        int k = i >> 3, c = i & 7;
        sw[i] = wsrc[(k << 10) + c];
    }
    if (tid < 128) g_hbuf[0][(jbase << 6) + tid] = 0.f;

    const int js = tid >> 6;
    const int jg = jbase + js;
    float c_state = 0.f;

    grid_barrier(1);

    const ulonglong2* swv = (const ulonglong2*)sw;

    for (int t = 0; t < TSTEP; t++) {
        float gx0, gx1, gx2, gx3;
        if (tid < 128) {
            const float* gp = g_gatesx + ((size_t)t << 16) + ((size_t)jg << 6) + row;
            gx0 = gp[0];
            gx1 = gp[256 * 64];
            gx2 = gp[512 * 64];
            gx3 = gp[768 * 64];
        }
        {
            const float4* hb = (const float4*)g_hbuf[t & 1];
            float4* sh4 = (float4*)sh;
            #pragma unroll
            for (int i = 0; i < 8; i++)
                sh4[tid + (i << 9)] = __ldcg(&hb[tid + (i << 9)]);
        }
        __syncthreads();

        // packed f32x2 accumulation: A0=(i,f) j0, A1=(g,o) j0, A2=(i,f) j1, A3=(g,o) j1
        unsigned long long A0 = 0ull, A1 = 0ull, A2 = 0ull, A3 = 0ull;
        const int k0 = oct << 5;
        #pragma unroll 8
        for (int kk = 0; kk < 32; kk++) {
            const int k = k0 + kk;
            ulonglong2 wa = swv[k << 1];         // sw[k*8 + 0..3]
            ulonglong2 wb = swv[(k << 1) + 1];   // sw[k*8 + 4..7]
            float hv = sh[(k << 6) + row];
            unsigned long long hh;
            asm("mov.b64 %0, {%1, %1};" : "=l"(hh) : "f"(hv));
            asm("fma.rn.f32x2 %0, %1, %2, %0;" : "+l"(A0) : "l"(wa.x), "l"(hh));
            asm("fma.rn.f32x2 %0, %1, %2, %0;" : "+l"(A1) : "l"(wa.y), "l"(hh));
            asm("fma.rn.f32x2 %0, %1, %2, %0;" : "+l"(A2) : "l"(wb.x), "l"(hh));
            asm("fma.rn.f32x2 %0, %1, %2, %0;" : "+l"(A3) : "l"(wb.y), "l"(hh));
        }
        float4 a0, a1;
        asm("mov.b64 {%0, %1}, %2;" : "=f"(a0.x), "=f"(a0.y) : "l"(A0));
        asm("mov.b64 {%0, %1}, %2;" : "=f"(a0.z), "=f"(a0.w) : "l"(A1));
        asm("mov.b64 {%0, %1}, %2;" : "=f"(a1.x), "=f"(a1.y) : "l"(A2));
        asm("mov.b64 {%0, %1}, %2;" : "=f"(a1.z), "=f"(a1.w) : "l"(A3));
        sp4[(oct << 7) + row]      = a0;
        sp4[(oct << 7) + 64 + row] = a1;
        __syncthreads();

        if (tid < 128) {
            float zi = gx0, zf = gx1, zg = gx2, zo = gx3;
            #pragma unroll
            for (int o = 0; o < 8; o++) {
                float4 z = sp4[(o << 7) + (js << 6) + row];
                zi += z.x; zf += z.y; zg += z.z; zo += z.w;
            }
            c_state = sigmoidf(zf) * c_state + sigmoidf(zi) * tanhf(zg);
            float hn = sigmoidf(zo) * tanhf(c_state);
            g_lstm[(((size_t)row * TSTEP + t) << 8) + jg] = hn;
            g_hbuf[(t + 1) & 1][(jg << 6) + row] = hn;
        }
        grid_barrier(t + 2);
    }

    // reset barrier state for the next graph replay
    if (tid == 0) {
        unsigned v;
        asm volatile("atom.add.release.gpu.u32 %0, [%1], 1;"
                     : "=r"(v) : "l"(&g_bar_cnt) : "memory");
        if (v == NCTA - 1) {
            g_bar_cnt = 0;
            asm volatile("st.release.gpu.u32 [%0], %1;"
                         :: "l"(&g_bar_phase), "r"(0u) : "memory");
        }
    }
}

// ---------------- pir head + value head fused (one block per row, 64 threads) --------
__global__ __launch_bounds__(64) void pir_kernel(const float* __restrict__ pir_W,
                                                 const float* __restrict__ pir_b,
                                                 const float* __restrict__ v_W,
                                                 const float* __restrict__ v_b)
{
    __shared__ float sh[256];
    __shared__ float lg[36];
    __shared__ float red[64];
    __shared__ float s_mx, s_sum;
    const int row = blockIdx.x;
    const int tid = threadIdx.x;
    for (int i = tid; i < 256; i += 64) sh[i] = g_lstm[(size_t)row * 256 + i];
    __syncthreads();

    // vpred partial (uses staged row)
    float vp = 0.f;
    #pragma unroll
    for (int k = tid; k < 256; k += 64) vp += sh[k] * v_W[k];

    // pir logits
    if (tid < 36) {
        float v = pir_b[tid];
        for (int k = 0; k < 256; k++) v += sh[k] * pir_W[k * 36 + tid];
        lg[tid] = v;
    }

    // reduce vpred
    red[tid] = vp; __syncthreads();
    for (int s = 32; s > 0; s >>= 1) { if (tid < s) red[tid] += red[tid + s]; __syncthreads(); }
    if (tid == 0) g_vpred[row] = red[0] + v_b[0];
    __syncthreads();

    // max
    red[tid] = (tid < 36) ? lg[tid] : -1e30f; __syncthreads();
    for (int s = 32; s > 0; s >>= 1) { if (tid < s) red[tid] = fmaxf(red[tid], red[tid + s]); __syncthreads(); }
    if (tid == 0) s_mx = red[0];
    __syncthreads();

    // sum exp
    float e = 0.f;
    if (tid < 36) e = expf(lg[tid] - s_mx);
    red[tid] = e; __syncthreads();
    for (int s = 32; s > 0; s >>= 1) { if (tid < s) red[tid] += red[tid + s]; __syncthreads(); }
    if (tid == 0) s_sum = red[0];
    __syncthreads();

    // probs + entropy
    float ent = 0.f;
    if (tid < 36) {
        float p = e / s_sum;
        g_pir[row * 36 + tid] = p;
        ent = p * logf(p);
    }
    red[tid] = ent; __syncthreads();
    for (int s = 32; s > 0; s >>= 1) { if (tid < s) red[tid] += red[tid + s]; __syncthreads(); }
    if (tid == 0) g_entpir[row] = red[0];
}

// ---------------- pim softmax: row cached in smem, single global read ----------------
__global__ __launch_bounds__(256) void pim_softmax_kernel(const int* __restrict__ mask,
                                                          const int* __restrict__ a_taken)
{
    __shared__ float sq[4096];
    __shared__ unsigned char sm8[4096];
    __shared__ float red[256];
    __shared__ float s_mx, s_S, s_SM;
    const int row = blockIdx.x;
    const int tid = threadIdx.x;
    const float4* __restrict__ lg4 = (const float4*)(g_pimlog + ((size_t)row << 12));
    const int4*   __restrict__ m4  = (const int4*)(mask + ((size_t)row << 12));

    float mx = -1e30f;
    for (int i = tid; i < 1024; i += 256) {
        float4 v = lg4[i];
        int4 m = m4[i];
        *(float4*)&sq[i << 2] = v;
        sm8[(i << 2) + 0] = (unsigned char)m.x;
        sm8[(i << 2) + 1] = (unsigned char)m.y;
        sm8[(i << 2) + 2] = (unsigned char)m.z;
        sm8[(i << 2) + 3] = (unsigned char)m.w;
        mx = fmaxf(mx, fmaxf(fmaxf(v.x, v.y), fmaxf(v.z, v.w)));
    }
    red[tid] = mx; __syncthreads();
    for (int s = 128; s > 0; s >>= 1) { if (tid < s) red[tid] = fmaxf(red[tid], red[tid + s]); __syncthreads(); }
    if (tid == 0) s_mx = red[0];
    __syncthreads();
    mx = s_mx;

    float ssum = 0.f, smsum = 0.f;
    for (int i = tid; i < 4096; i += 256) {
        float qv = expf(sq[i] - mx);
        sq[i] = qv;
        ssum += qv;
        if (sm8[i]) smsum += qv;
    }
    __syncthreads();
    red[tid] = ssum; __syncthreads();
    for (int s = 128; s > 0; s >>= 1) { if (tid < s) red[tid] += red[tid + s]; __syncthreads(); }
    if (tid == 0) s_S = red[0];
    __syncthreads();
    red[tid] = smsum; __syncthreads();
    for (int s = 128; s > 0; s >>= 1) { if (tid < s) red[tid] += red[tid + s]; __syncthreads(); }
    if (tid == 0) s_SM = red[0];
    __syncthreads();

    const float denom = (s_SM > 0.f) ? s_SM : s_S;

    float ent = 0.f;
    for (int i = tid; i < 4096; i += 256) {
        if (sm8[i]) {
            float p = sq[i] / denom;
            if (p > 0.f) ent += p * logf(p);
        }
    }
    __syncthreads();
    red[tid] = ent; __syncthreads();
    for (int s = 128; s > 0; s >>= 1) { if (tid < s) red[tid] += red[tid + s]; __syncthreads(); }
    if (tid == 0) {
        g_entpim[row] = red[0];
        int a = a_taken[row];
        g_ppim[row] = sm8[a] ? sq[a] / denom : 0.f;
    }
}

// ---------------- block-wide double sum (blockDim must be 1024) ----------------
__device__ double block_sum_d(double v)
{
    __shared__ double rd[1024];
    const int tid = threadIdx.x;
    __syncthreads();
    rd[tid] = v; __syncthreads();
    for (int s = 512; s > 0; s >>= 1) { if (tid < s) rd[tid] += rd[tid + s]; __syncthreads(); }
    double r = rd[0];
    __syncthreads();
    return r;
}

__global__ __launch_bounds__(1024) void gae_stats_kernel(const float* __restrict__ GAE)
{
    const int tid = threadIdx.x;
    double s = 0.0;
    for (int i = tid; i < BT; i += 1024) s += (double)GAE[i];
    double tot = block_sum_d(s);
    double mean = tot / (double)BT;
    double v = 0.0;
    for (int i = tid; i < BT; i += 1024) { double d = (double)GAE[i] - mean; v += d * d; }
    double var = block_sum_d(v) / (double)BT;
    if (tid == 0) { g_stats[0] = (float)mean; g_stats[1] = (float)sqrt(var); }
}

__global__ void pg_terms_kernel(const float* __restrict__ lg_old,
                                const int* __restrict__ a_taken,
                                const float* __restrict__ GAE)
{
    const int i = blockIdx.x * blockDim.x + threadIdx.x;
    if (i >= BT) return;
    const float mean = g_stats[0], std = g_stats[1];
    float g = (GAE[i] - mean) / (std + 1e-8f);
    int a = a_taken[i];
    float p = ((i & 1) == 0) ? g_pir[i * 36 + a] : g_ppim[i];
    float lgn = logf(p);
    float rt = expf(lgn - lg_old[i]);
    float rtc = fminf(fmaxf(rt, 0.8f), 1.2f);
    g_pgvals[i] = fmaxf(-g * rt, -g * rtc);
}

// vf broadcast loss: 128 blocks x 32 rows, ret/old_v cached in smem, warp-per-row
__global__ __launch_bounds__(256) void vf_kernel(const float* __restrict__ old_v,
                                                 const float* __restrict__ ret)
{
    __shared__ float sret[BT];
    __shared__ float sov[BT];
    const int tid = threadIdx.x;
    for (int j = tid; j < BT; j += 256) { sret[j] = ret[j]; sov[j] = old_v[j]; }
    __syncthreads();
    const int warp = tid >> 5, lane = tid & 31;
    #pragma unroll
    for (int ii = 0; ii < 4; ii++) {
        const int i = blockIdx.x * 32 + ii * 8 + warp;
        const float vp = g_vpred[i];
        float s = 0.f;
        for (int j = lane; j < BT; j += 32) {
            float r = sret[j];
            float ov = sov[j];
            float d1 = vp - r;
            float dc = fminf(fmaxf(vp - ov, -0.2f), 0.2f);
            float d2 = ov + dc - r;
            s += fmaxf(d1 * d1, d2 * d2);
        }
        #pragma unroll
        for (int o = 16; o > 0; o >>= 1) s += __shfl_down_sync(0xffffffffu, s, o);
        if (lane == 0) g_vfvals[i] = s;
    }
}

__global__ __launch_bounds__(1024) void finalize_kernel(float* __restrict__ out)
{
    const int tid = threadIdx.x;
    double s = 0.0;
    for (int i = tid; i < BT; i += 1024) s += (double)g_pgvals[i];
    double pg = block_sum_d(s) / (double)BT;

    s = 0.0;
    for (int i = tid; i < BT; i += 1024) s += (double)g_entpir[i] + (double)g_entpim[i];
    double entropy = -block_sum_d(s);

    s = 0.0;
    for (int i = tid; i < BT; i += 1024) s += (double)g_vfvals[i];
    double vf = 0.5 * block_sum_d(s) / ((double)BT * (double)BT);

    if (tid == 0) {
        out[0] = (float)(pg - entropy + vf);
        out[1] = (float)pg;
        out[2] = (float)entropy;
        out[3] = (float)vf;
    }
}

// ---------------- launcher ----------------
extern "C" void kernel_launch(void* const* d_in, const int* in_sizes, int n_in,
                              void* d_out, int out_size)
{
    const float* x       = (const float*)d_in[0];
    const int*   mask    = (const int*)  d_in[1];
    const float* lg_old  = (const float*)d_in[2];
    const int*   a_taken = (const int*)  d_in[3];
    const float* GAE     = (const float*)d_in[4];
    const float* old_v   = (const float*)d_in[5];
    const float* rets    = (const float*)d_in[6];
    const float* W1 = (const float*)d_in[7];  const float* b1 = (const float*)d_in[8];
    const float* W2 = (const float*)d_in[9];  const float* b2 = (const float*)d_in[10];
    const float* W3 = (const float*)d_in[11]; const float* b3 = (const float*)d_in[12];
    const float* W4 = (const float*)d_in[13]; const float* b4 = (const float*)d_in[14];
    const float* lstm_k = (const float*)d_in[15];
    const float* lstm_r = (const float*)d_in[16];
    const float* lstm_b = (const float*)d_in[17];
    const float* pir_W  = (const float*)d_in[18];
    const float* pir_b  = (const float*)d_in[19];
    const float* pim_W  = (const float*)d_in[20];
    const float* pim_b  = (const float*)d_in[21];
    const float* v_W    = (const float*)d_in[22];
    const float* v_b    = (const float*)d_in[23];
    float* out = (float*)d_out;

    void *p_feat, *p_gatesx, *p_lstm, *p_pimlog, *p_Asp, *p_Bpim, *p_Bk;
    cudaGetSymbolAddress(&p_feat,   g_feat);
    cudaGetSymbolAddress(&p_gatesx, g_gatesx);
    cudaGetSymbolAddress(&p_lstm,   g_lstm);
    cudaGetSymbolAddress(&p_pimlog, g_pimlog);
    cudaGetSymbolAddress(&p_Asp,    g_Asp);
    cudaGetSymbolAddress(&p_Bpim,   g_Bpim);
    cudaGetSymbolAddress(&p_Bk,     g_Bk);

    cudaFuncSetAttribute(lstm_persist_kernel,
                         cudaFuncAttributeMaxDynamicSharedMemorySize, LSTM_SMEM_BYTES);
    cudaFuncSetAttribute(bf16_gemm_ps_kernel,
                         cudaFuncAttributeMaxDynamicSharedMemorySize, PS_SMEM_BYTES);

    conv_kernel<<<BT, 128>>>(x, W1, b1, W2, b2, W3, b3, W4, b4);
    pack_wr_kernel<<<1024, 256>>>(lstm_r);
    splitB_kernel<<<512, 256>>>(lstm_k, (uint2*)p_Bk, 1024);
    splitB_kernel<<<2048, 256>>>(pim_W, (uint2*)p_Bpim, 4096);
    split_tr4096_kernel<<<2048, 256>>>((const float*)p_feat, (uint2*)p_Asp, 256);

    // gates_x = feat @ lstm_k + lstm_b (4096x1024), transposed epilogue [t][gcol][b]
    bf16_gemm_ps_kernel<<<dim3(8, 32), 256, PS_SMEM_BYTES>>>(
        (const uint2*)p_Asp, (const uint2*)p_Bk, lstm_b, (float*)p_gatesx,
        BT, 1024, 128, 1);

    lstm_persist_kernel<<<NCTA, 512, LSTM_SMEM_BYTES>>>();

    split_tr4096_kernel<<<2048, 256>>>((const float*)p_lstm, (uint2*)p_Asp, 256);

    // pim logits = lstm @ pim_W + pim_b (4096x4096)
    bf16_gemm_ps_kernel<<<dim3(32, 32), 256, PS_SMEM_BYTES>>>(
        (const uint2*)p_Asp, (const uint2*)p_Bpim, pim_b, (float*)p_pimlog,
        BT, 4096, 128, 0);

    pir_kernel<<<BT, 64>>>(pir_W, pir_b, v_W, v_b);
    pim_softmax_kernel<<<BT, 256>>>(mask, a_taken);
    gae_stats_kernel<<<1, 1024>>>(GAE);
    pg_terms_kernel<<<16, 256>>>(lg_old, a_taken, GAE);
    vf_kernel<<<128, 256>>>(old_v, rets);
    finalize_kernel<<<1, 1024>>>(out);
}

// round 15
// speedup vs baseline: 1.5404x; 1.5404x over previous
#include <cuda_runtime.h>
#include <cuda_bf16.h>
#include <math.h>
#include <stdint.h>

#define BT    4096
#define HID   256
#define TSTEP 64
#define BB    64
#define NCTA  128

// ---------------- scratch (static device memory; no allocations) ----------------
__device__ float g_feat  [BT * HID];          // conv features (B*T, 256)
__device__ float g_gatesx[BT * 1024];         // x @ Wk + b, TRANSPOSED: [t][gatecol][b]
__device__ float g_lstm  [BT * HID];          // lstm hidden states
__device__ float g_Wr4   [256 * 1024];        // Wr packed: [k][j][gate] interleaved
__device__ float g_hbuf  [2][16384];          // LSTM h double buffer, [j][b]
__device__ float g_pimlog[16777216];          // pim logits (4096 x 4096)
__device__ uint2 g_Asp   [128 * 4096];        // split activations [kpair][m] (hi-pair, lo-pair)
__device__ uint2 g_Bpim  [128 * 4096];        // split pim_W [kpair][n]
__device__ uint2 g_Bk    [128 * 1024];        // split lstm_k [kpair][n]
__device__ float g_pir   [BT * 36];           // pir probabilities
__device__ float g_entpir[BT];
__device__ float g_entpim[BT];
__device__ float g_ppim  [BT];                // pim prob of taken action
__device__ float g_vpred [BT];
__device__ float g_pgvals[BT];
__device__ float g_vfvals[BT];
__device__ float g_stats [2];                 // gae mean, std
__device__ unsigned g_bar_cnt = 0;            // grid barrier arrive counter
__device__ unsigned g_bar_phase = 0;          // grid barrier phase flag

__device__ __forceinline__ float leaky(float v) { return v > 0.f ? v : 0.2f * v; }
__device__ __forceinline__ float sigmoidf(float v) { return 1.f / (1.f + expf(-v)); }

__device__ __forceinline__ uint32_t smem_u32(const void* p)
{
    uint32_t a;
    asm("{ .reg .u64 t; cvta.to.shared.u64 t, %1; cvt.u32.u64 %0, t; }" : "=r"(a) : "l"(p));
    return a;
}

__device__ __forceinline__ void cp_async16(uint32_t dst, const void* src)
{
    asm volatile("cp.async.cg.shared.global [%0], [%1], 16;" :: "r"(dst), "l"(src));
}

// ---------------- fused conv stack: one block per image ----------------
__global__ __launch_bounds__(128) void conv_kernel(
    const float* __restrict__ x,
    const float* __restrict__ W1, const float* __restrict__ b1,
    const float* __restrict__ W2, const float* __restrict__ b2,
    const float* __restrict__ W3, const float* __restrict__ b3,
    const float* __restrict__ W4, const float* __restrict__ b4)
{
    __shared__ float sx[832];   // 13*8*8
    __shared__ float h1[384];   // 6*4*16
    __shared__ float h2[480];   // 5*3*32
    __shared__ float h3[128];   // 2*1*64
    const int img = blockIdx.x;
    const float* xin = x + img * 832;
    for (int i = threadIdx.x; i < 832; i += blockDim.x) sx[i] = xin[i];
    __syncthreads();

    // conv1: (13,8,8) -> (6,4,16), k=2 s=2
    for (int idx = threadIdx.x; idx < 384; idx += blockDim.x) {
        int oc = idx & 15, sp = idx >> 4;
        int ow = sp & 3, oh = sp >> 2;
        float v = b1[oc];
        #pragma unroll
        for (int kh = 0; kh < 2; kh++)
        #pragma unroll
        for (int kw = 0; kw < 2; kw++) {
            const float* xp = &sx[((oh * 2 + kh) * 8 + (ow * 2 + kw)) * 8];
            const float* wp = &W1[((kh * 2 + kw) * 8) * 16 + oc];
            #pragma unroll
            for (int ic = 0; ic < 8; ic++) v += xp[ic] * wp[ic * 16];
        }
        h1[idx] = leaky(v);
    }
    __syncthreads();

    // conv2: (6,4,16) -> (5,3,32), k=2 s=1
    for (int idx = threadIdx.x; idx < 480; idx += blockDim.x) {
        int oc = idx & 31, sp = idx >> 5;
        int ow = sp % 3, oh = sp / 3;
        float v = b2[oc];
        #pragma unroll
        for (int kh = 0; kh < 2; kh++)
        #pragma unroll
        for (int kw = 0; kw < 2; kw++) {
            const float* hp = &h1[((oh + kh) * 4 + (ow + kw)) * 16];
            const float* wp = &W2[((kh * 2 + kw) * 16) * 32 + oc];
            #pragma unroll
            for (int ic = 0; ic < 16; ic++) v += hp[ic] * wp[ic * 32];
        }
        h2[idx] = leaky(v);
    }
    __syncthreads();

    // conv3: (5,3,32) -> (2,1,64), k=2 s=2
    for (int idx = threadIdx.x; idx < 128; idx += blockDim.x) {
        int oc = idx & 63, oh = idx >> 6;
        float v = b3[oc];
        #pragma unroll
        for (int kh = 0; kh < 2; kh++)
        #pragma unroll
        for (int kw = 0; kw < 2; kw++) {
            const float* hp = &h2[((oh * 2 + kh) * 3 + kw) * 32];
            const float* wp = &W3[((kh * 2 + kw) * 32) * 64 + oc];
            #pragma unroll
            for (int ic = 0; ic < 32; ic++) v += hp[ic] * wp[ic * 64];
        }
        h3[idx] = leaky(v);
    }
    __syncthreads();

    // conv4 1x1: (2,1,64)->(2,1,128) + channels_first flatten: feat[2*oc+oh]
    for (int idx = threadIdx.x; idx < 256; idx += blockDim.x) {
        int oc = idx >> 1, oh = idx & 1;
        float v = b4[oc];
        #pragma unroll
        for (int ic = 0; ic < 64; ic++) v += h3[oh * 64 + ic] * W4[ic * 128 + oc];
        g_feat[img * 256 + idx] = leaky(v);
    }
}

// ---------------- bf16 hi/lo split helpers ----------------
__device__ __forceinline__ uint2 split_bf16pair(float a0, float a1)
{
    __nv_bfloat16 h0 = __float2bfloat16(a0);
    __nv_bfloat16 h1 = __float2bfloat16(a1);
    float r0 = a0 - __bfloat162float(h0);
    float r1 = a1 - __bfloat162float(h1);
    __nv_bfloat162 hp = __halves2bfloat162(h0, h1);
    __nv_bfloat162 lp = __halves2bfloat162(__float2bfloat16(r0), __float2bfloat16(r1));
    uint2 r;
    r.x = *(const uint32_t*)&hp;
    r.y = *(const uint32_t*)&lp;
    return r;
}

// split + transpose: src [4096][K] f32 -> dst [K/2][4096] uint2
__global__ __launch_bounds__(256) void split_tr4096_kernel(const float* __restrict__ src,
                                                           uint2* __restrict__ dst, int K)
{
    int idx = blockIdx.x * 256 + threadIdx.x;
    int kp = idx >> 12, m = idx & 4095;
    float2 a = *(const float2*)&src[(size_t)m * K + 2 * kp];
    dst[idx] = split_bf16pair(a.x, a.y);
}

// split B [K][N] f32 -> [K/2][N] uint2
__global__ __launch_bounds__(256) void splitB_kernel(const float* __restrict__ src,
                                                     uint2* __restrict__ dst, int N)
{
    int idx = blockIdx.x * 256 + threadIdx.x;
    int kp = idx / N, n = idx - kp * N;
    float a0 = src[(size_t)(2 * kp) * N + n];
    float a1 = src[(size_t)(2 * kp + 1) * N + n];
    dst[idx] = split_bf16pair(a0, a1);
}

// ---------------- 3xBF16 tensor GEMM (m16n8k16), pre-split inputs, cp.async ----------
#define MMA_BF16(d, a, b0v, b1v) \
    asm volatile("mma.sync.aligned.m16n8k16.row.col.f32.bf16.bf16.f32 " \
        "{%0,%1,%2,%3}, {%4,%5,%6,%7}, {%8,%9}, {%0,%1,%2,%3};" \
        : "+f"((d)[0]), "+f"((d)[1]), "+f"((d)[2]), "+f"((d)[3]) \
        : "r"((a)[0]), "r"((a)[1]), "r"((a)[2]), "r"((a)[3]), "r"(b0v), "r"(b1v))

#define PS_TILE  1056                 // 8 kpair rows * 132 uint2
#define PS_SMEM_BYTES (4 * PS_TILE * 8)

__device__ __forceinline__ void load_tiles_ps(uint2* Asb, uint2* Bsb,
    const uint2* __restrict__ A, const uint2* __restrict__ B,
    int M, int N, int m0, int n0, int kp0, int tid)
{
    #pragma unroll
    for (int i = 0; i < 2; i++) {
        int r  = (tid >> 6) + (i << 2);
        int cc = (tid & 63) << 1;
        cp_async16(smem_u32(Asb + r * 132 + cc), A + (size_t)(kp0 + r) * M + m0 + cc);
        cp_async16(smem_u32(Bsb + r * 132 + cc), B + (size_t)(kp0 + r) * N + n0 + cc);
    }
}

__global__ __launch_bounds__(256) void bf16_gemm_ps_kernel(
    const uint2* __restrict__ A, const uint2* __restrict__ B,
    const float* __restrict__ bias, float* __restrict__ C,
    int M, int N, int K2, int trans_out)
{
    extern __shared__ uint2 ps[];
    uint2* As0 = ps;
    uint2* Bs0 = ps + 2 * PS_TILE;
    const int tid  = threadIdx.x;
    const int lane = tid & 31, warp = tid >> 5;
    const int wm = warp & 3, wn = warp >> 2;
    const int g = lane >> 2, tg = lane & 3;
    const int m0 = blockIdx.y * 128, n0 = blockIdx.x * 128;

    float acc[2][8][4];
    #pragma unroll
    for (int a = 0; a < 2; a++)
        #pragma unroll
        for (int b = 0; b < 8; b++)
            #pragma unroll
            for (int c = 0; c < 4; c++) acc[a][b][c] = 0.f;

    load_tiles_ps(As0, Bs0, A, B, M, N, m0, n0, 0, tid);
    asm volatile("cp.async.commit_group;" ::: "memory");

    int st = 0;
    for (int kp0 = 0; kp0 < K2; kp0 += 8) {
        if (kp0 + 8 < K2) {
            load_tiles_ps(As0 + (st ^ 1) * PS_TILE, Bs0 + (st ^ 1) * PS_TILE,
                          A, B, M, N, m0, n0, kp0 + 8, tid);
            asm volatile("cp.async.commit_group;" ::: "memory");
            asm volatile("cp.async.wait_group 1;" ::: "memory");
        } else {
            asm volatile("cp.async.wait_group 0;" ::: "memory");
        }
        __syncthreads();

        const uint2* Ac = As0 + st * PS_TILE;
        const uint2* Bc = Bs0 + st * PS_TILE;

        uint32_t ah[2][4], al[2][4];
        #pragma unroll
        for (int mt = 0; mt < 2; mt++) {
            const int rb = wm * 32 + mt * 16;
            uint2 x0 = Ac[tg * 132 + rb + g];
            uint2 x1 = Ac[tg * 132 + rb + g + 8];
            uint2 x2 = Ac[(tg + 4) * 132 + rb + g];
            uint2 x3 = Ac[(tg + 4) * 132 + rb + g + 8];
            ah[mt][0] = x0.x; al[mt][0] = x0.y;
            ah[mt][1] = x1.x; al[mt][1] = x1.y;
            ah[mt][2] = x2.x; al[mt][2] = x2.y;
            ah[mt][3] = x3.x; al[mt][3] = x3.y;
        }
        #pragma unroll
        for (int nt = 0; nt < 8; nt++) {
            const int nb = wn * 64 + nt * 8 + g;
            uint2 y0 = Bc[tg * 132 + nb];
            uint2 y1 = Bc[(tg + 4) * 132 + nb];
            #pragma unroll
            for (int mt = 0; mt < 2; mt++) {
                MMA_BF16(acc[mt][nt], ah[mt], y0.x, y1.x);  // hi*hi
                MMA_BF16(acc[mt][nt], al[mt], y0.x, y1.x);  // lo*hi
                MMA_BF16(acc[mt][nt], ah[mt], y0.y, y1.y);  // hi*lo
            }
        }
        __syncthreads();
        st ^= 1;
    }

    #pragma unroll
    for (int mt = 0; mt < 2; mt++) {
        const int r0 = m0 + wm * 32 + mt * 16 + g;
        #pragma unroll
        for (int nt = 0; nt < 8; nt++) {
            const int col = n0 + wn * 64 + nt * 8 + 2 * tg;
            const float b0v = bias[col], b1v = bias[col + 1];
            if (!trans_out) {
                *(float2*)&C[(size_t)r0 * N + col] =
                    make_float2(acc[mt][nt][0] + b0v, acc[mt][nt][1] + b1v);
                *(float2*)&C[(size_t)(r0 + 8) * N + col] =
                    make_float2(acc[mt][nt][2] + b0v, acc[mt][nt][3] + b1v);
            } else {
                int t0 = r0 & 63, bb0 = r0 >> 6;
                int t1 = (r0 + 8) & 63, bb1 = (r0 + 8) >> 6;
                C[((size_t)t0 << 16) + ((size_t)col << 6) + bb0]       = acc[mt][nt][0] + b0v;
                C[((size_t)t0 << 16) + ((size_t)(col + 1) << 6) + bb0] = acc[mt][nt][1] + b1v;
                C[((size_t)t1 << 16) + ((size_t)col << 6) + bb1]       = acc[mt][nt][2] + b0v;
                C[((size_t)t1 << 16) + ((size_t)(col + 1) << 6) + bb1] = acc[mt][nt][3] + b1v;
            }
        }
    }
}

// ---------------- pack Wr: Wr[k*1024 + g*256 + j] -> g_Wr4[k*1024 + j*4 + g] ----------------
__global__ __launch_bounds__(256) void pack_wr_kernel(const float* __restrict__ Wr)
{
    int idx = blockIdx.x * 256 + threadIdx.x;
    int k = idx >> 10, col = idx & 1023;
    int g = col >> 8, j = col & 255;
    g_Wr4[(k << 10) + (j << 2) + g] = Wr[idx];
}

// ---------------- LSTM: persistent full-chip kernel, release/acquire grid barrier ----------
#define LSTM_SMEM_BYTES ((2048 + 16384 + 4096) * 4)

__device__ __forceinline__ void grid_barrier(unsigned target)
{
    __syncthreads();
    if (threadIdx.x == 0) {
        unsigned v;
        asm volatile("atom.add.release.gpu.u32 %0, [%1], 1;"
                     : "=r"(v) : "l"(&g_bar_cnt) : "memory");
        if (v == NCTA - 1) {
            g_bar_cnt = 0;
            asm volatile("st.release.gpu.u32 [%0], %1;"
                         :: "l"(&g_bar_phase), "r"(target) : "memory");
        } else {
            unsigned p;
            do {
                asm volatile("ld.acquire.gpu.u32 %0, [%1];"
                             : "=r"(p) : "l"(&g_bar_phase) : "memory");
            } while (p < target);
        }
    }
    __syncthreads();
}

__global__ __launch_bounds__(512) void lstm_persist_kernel()
{
    extern __shared__ float smem[];
    float*  sw  = smem;                       // [k*8 + c] weight slice, 2048 floats
    float*  sh  = smem + 2048;                // h tile [k*64 + b], 16384 floats
    float4* sp4 = (float4*)(smem + 2048 + 16384); // partials

    const int tid = threadIdx.x;
    const int row = tid & 63;
    const int oct = tid >> 6;
    const int jbase = blockIdx.x << 1;

    const float* wsrc = g_Wr4 + (jbase << 2);
    for (int i = tid; i < 2048; i += 512) {
        int k = i >> 3, c = i & 7;
        sw[i] = wsrc[(k << 10) + c];
    }
    if (tid < 128) g_hbuf[0][(jbase << 6) + tid] = 0.f;

    const int js = tid >> 6;
    const int jg = jbase + js;
    float c_state = 0.f;

    grid_barrier(1);

    for (int t = 0; t < TSTEP; t++) {
        float gx0, gx1, gx2, gx3;
        if (tid < 128) {
            const float* gp = g_gatesx + ((size_t)t << 16) + ((size_t)jg << 6) + row;
            gx0 = gp[0];
            gx1 = gp[256 * 64];
            gx2 = gp[512 * 64];
            gx3 = gp[768 * 64];
        }
        {
            const float4* hb = (const float4*)g_hbuf[t & 1];
            float4* sh4 = (float4*)sh;
            #pragma unroll
            for (int i = 0; i < 8; i++)
                sh4[tid + (i << 9)] = __ldcg(&hb[tid + (i << 9)]);
        }
        __syncthreads();

        float4 a0 = make_float4(0.f, 0.f, 0.f, 0.f);
        float4 a1 = make_float4(0.f, 0.f, 0.f, 0.f);
        const int k0 = oct << 5;
        #pragma unroll 8
        for (int kk = 0; kk < 32; kk++) {
            const int k = k0 + kk;
            float4 w0 = *(const float4*)&sw[k << 3];
            float4 w1 = *(const float4*)&sw[(k << 3) + 4];
            float hv = sh[(k << 6) + row];
            a0.x += w0.x * hv; a0.y += w0.y * hv; a0.z += w0.z * hv; a0.w += w0.w * hv;
            a1.x += w1.x * hv; a1.y += w1.y * hv; a1.z += w1.z * hv; a1.w += w1.w * hv;
        }
        sp4[(oct << 7) + row]      = a0;
        sp4[(oct << 7) + 64 + row] = a1;
        __syncthreads();

        if (tid < 128) {
            float zi = gx0, zf = gx1, zg = gx2, zo = gx3;
            #pragma unroll
            for (int o = 0; o < 8; o++) {
                float4 z = sp4[(o << 7) + (js << 6) + row];
                zi += z.x; zf += z.y; zg += z.z; zo += z.w;
            }
            c_state = sigmoidf(zf) * c_state + sigmoidf(zi) * tanhf(zg);
            float hn = sigmoidf(zo) * tanhf(c_state);
            g_lstm[(((size_t)row * TSTEP + t) << 8) + jg] = hn;
            g_hbuf[(t + 1) & 1][(jg << 6) + row] = hn;
        }
        grid_barrier(t + 2);
    }

    // reset barrier state for the next graph replay
    if (tid == 0) {
        unsigned v;
        asm volatile("atom.add.release.gpu.u32 %0, [%1], 1;"
                     : "=r"(v) : "l"(&g_bar_cnt) : "memory");
        if (v == NCTA - 1) {
            g_bar_cnt = 0;
            asm volatile("st.release.gpu.u32 [%0], %1;"
                         :: "l"(&g_bar_phase), "r"(0u) : "memory");
        }
    }
}

// ---------------- pir head + value head fused (one block per row, 64 threads) --------
__global__ __launch_bounds__(64) void pir_kernel(const float* __restrict__ pir_W,
                                                 const float* __restrict__ pir_b,
                                                 const float* __restrict__ v_W,
                                                 const float* __restrict__ v_b)
{
    __shared__ float sh[256];
    __shared__ float lg[36];
    __shared__ float red[64];
    __shared__ float s_mx, s_sum;
    const int row = blockIdx.x;
    const int tid = threadIdx.x;
    for (int i = tid; i < 256; i += 64) sh[i] = g_lstm[(size_t)row * 256 + i];
    __syncthreads();

    // vpred partial (uses staged row)
    float vp = 0.f;
    #pragma unroll
    for (int k = tid; k < 256; k += 64) vp += sh[k] * v_W[k];

    // pir logits
    if (tid < 36) {
        float v = pir_b[tid];
        for (int k = 0; k < 256; k++) v += sh[k] * pir_W[k * 36 + tid];
        lg[tid] = v;
    }

    // reduce vpred
    red[tid] = vp; __syncthreads();
    for (int s = 32; s > 0; s >>= 1) { if (tid < s) red[tid] += red[tid + s]; __syncthreads(); }
    if (tid == 0) g_vpred[row] = red[0] + v_b[0];
    __syncthreads();

    // max
    red[tid] = (tid < 36) ? lg[tid] : -1e30f; __syncthreads();
    for (int s = 32; s > 0; s >>= 1) { if (tid < s) red[tid] = fmaxf(red[tid], red[tid + s]); __syncthreads(); }
    if (tid == 0) s_mx = red[0];
    __syncthreads();

    // sum exp
    float e = 0.f;
    if (tid < 36) e = expf(lg[tid] - s_mx);
    red[tid] = e; __syncthreads();
    for (int s = 32; s > 0; s >>= 1) { if (tid < s) red[tid] += red[tid + s]; __syncthreads(); }
    if (tid == 0) s_sum = red[0];
    __syncthreads();

    // probs + entropy
    float ent = 0.f;
    if (tid < 36) {
        float p = e / s_sum;
        g_pir[row * 36 + tid] = p;
        ent = p * logf(p);
    }
    red[tid] = ent; __syncthreads();
    for (int s = 32; s > 0; s >>= 1) { if (tid < s) red[tid] += red[tid + s]; __syncthreads(); }
    if (tid == 0) g_entpir[row] = red[0];
}

// ---------------- pim softmax: row cached in smem, single global read ----------------
__global__ __launch_bounds__(256) void pim_softmax_kernel(const int* __restrict__ mask,
                                                          const int* __restrict__ a_taken)
{
    __shared__ float sq[4096];
    __shared__ unsigned char sm8[4096];
    __shared__ float red[256];
    __shared__ float s_mx, s_S, s_SM;
    const int row = blockIdx.x;
    const int tid = threadIdx.x;
    const float4* __restrict__ lg4 = (const float4*)(g_pimlog + ((size_t)row << 12));
    const int4*   __restrict__ m4  = (const int4*)(mask + ((size_t)row << 12));

    float mx = -1e30f;
    for (int i = tid; i < 1024; i += 256) {
        float4 v = lg4[i];
        int4 m = m4[i];
        *(float4*)&sq[i << 2] = v;
        sm8[(i << 2) + 0] = (unsigned char)m.x;
        sm8[(i << 2) + 1] = (unsigned char)m.y;
        sm8[(i << 2) + 2] = (unsigned char)m.z;
        sm8[(i << 2) + 3] = (unsigned char)m.w;
        mx = fmaxf(mx, fmaxf(fmaxf(v.x, v.y), fmaxf(v.z, v.w)));
    }
    red[tid] = mx; __syncthreads();
    for (int s = 128; s > 0; s >>= 1) { if (tid < s) red[tid] = fmaxf(red[tid], red[tid + s]); __syncthreads(); }
    if (tid == 0) s_mx = red[0];
    __syncthreads();
    mx = s_mx;

    float ssum = 0.f, smsum = 0.f;
    for (int i = tid; i < 4096; i += 256) {
        float qv = expf(sq[i] - mx);
        sq[i] = qv;
        ssum += qv;
        if (sm8[i]) smsum += qv;
    }
    __syncthreads();
    red[tid] = ssum; __syncthreads();
    for (int s = 128; s > 0; s >>= 1) { if (tid < s) red[tid] += red[tid + s]; __syncthreads(); }
    if (tid == 0) s_S = red[0];
    __syncthreads();
    red[tid] = smsum; __syncthreads();
    for (int s = 128; s > 0; s >>= 1) { if (tid < s) red[tid] += red[tid + s]; __syncthreads(); }
    if (tid == 0) s_SM = red[0];
    __syncthreads();

    const float denom = (s_SM > 0.f) ? s_SM : s_S;

    float ent = 0.f;
    for (int i = tid; i < 4096; i += 256) {
        if (sm8[i]) {
            float p = sq[i] / denom;
            if (p > 0.f) ent += p * logf(p);
        }
    }
    __syncthreads();
    red[tid] = ent; __syncthreads();
    for (int s = 128; s > 0; s >>= 1) { if (tid < s) red[tid] += red[tid + s]; __syncthreads(); }
    if (tid == 0) {
        g_entpim[row] = red[0];
        int a = a_taken[row];
        g_ppim[row] = sm8[a] ? sq[a] / denom : 0.f;
    }
}

// ---------------- block-wide double sum (blockDim must be 1024) ----------------
__device__ double block_sum_d(double v)
{
    __shared__ double rd[1024];
    const int tid = threadIdx.x;
    __syncthreads();
    rd[tid] = v; __syncthreads();
    for (int s = 512; s > 0; s >>= 1) { if (tid < s) rd[tid] += rd[tid + s]; __syncthreads(); }
    double r = rd[0];
    __syncthreads();
    return r;
}

__global__ __launch_bounds__(1024) void gae_stats_kernel(const float* __restrict__ GAE)
{
    const int tid = threadIdx.x;
    double s = 0.0;
    for (int i = tid; i < BT; i += 1024) s += (double)GAE[i];
    double tot = block_sum_d(s);
    double mean = tot / (double)BT;
    double v = 0.0;
    for (int i = tid; i < BT; i += 1024) { double d = (double)GAE[i] - mean; v += d * d; }
    double var = block_sum_d(v) / (double)BT;
    if (tid == 0) { g_stats[0] = (float)mean; g_stats[1] = (float)sqrt(var); }
}

__global__ void pg_terms_kernel(const float* __restrict__ lg_old,
                                const int* __restrict__ a_taken,
                                const float* __restrict__ GAE)
{
    const int i = blockIdx.x * blockDim.x + threadIdx.x;
    if (i >= BT) return;
    const float mean = g_stats[0], std = g_stats[1];
    float g = (GAE[i] - mean) / (std + 1e-8f);
    int a = a_taken[i];
    float p = ((i & 1) == 0) ? g_pir[i * 36 + a] : g_ppim[i];
    float lgn = logf(p);
    float rt = expf(lgn - lg_old[i]);
    float rtc = fminf(fmaxf(rt, 0.8f), 1.2f);
    g_pgvals[i] = fmaxf(-g * rt, -g * rtc);
}

// vf broadcast loss: 128 blocks x 32 rows, ret/old_v cached in smem, warp-per-row
__global__ __launch_bounds__(256) void vf_kernel(const float* __restrict__ old_v,
                                                 const float* __restrict__ ret)
{
    __shared__ float sret[BT];
    __shared__ float sov[BT];
    const int tid = threadIdx.x;
    for (int j = tid; j < BT; j += 256) { sret[j] = ret[j]; sov[j] = old_v[j]; }
    __syncthreads();
    const int warp = tid >> 5, lane = tid & 31;
    #pragma unroll
    for (int ii = 0; ii < 4; ii++) {
        const int i = blockIdx.x * 32 + ii * 8 + warp;
        const float vp = g_vpred[i];
        float s = 0.f;
        for (int j = lane; j < BT; j += 32) {
            float r = sret[j];
            float ov = sov[j];
            float d1 = vp - r;
            float dc = fminf(fmaxf(vp - ov, -0.2f), 0.2f);
            float d2 = ov + dc - r;
            s += fmaxf(d1 * d1, d2 * d2);
        }
        #pragma unroll
        for (int o = 16; o > 0; o >>= 1) s += __shfl_down_sync(0xffffffffu, s, o);
        if (lane == 0) g_vfvals[i] = s;
    }
}

__global__ __launch_bounds__(1024) void finalize_kernel(float* __restrict__ out)
{
    const int tid = threadIdx.x;
    double s = 0.0;
    for (int i = tid; i < BT; i += 1024) s += (double)g_pgvals[i];
    double pg = block_sum_d(s) / (double)BT;

    s = 0.0;
    for (int i = tid; i < BT; i += 1024) s += (double)g_entpir[i] + (double)g_entpim[i];
    double entropy = -block_sum_d(s);

    s = 0.0;
    for (int i = tid; i < BT; i += 1024) s += (double)g_vfvals[i];
    double vf = 0.5 * block_sum_d(s) / ((double)BT * (double)BT);

    if (tid == 0) {
        out[0] = (float)(pg - entropy + vf);
        out[1] = (float)pg;
        out[2] = (float)entropy;
        out[3] = (float)vf;
    }
}

// ---------------- launcher ----------------
extern "C" void kernel_launch(void* const* d_in, const int* in_sizes, int n_in,
                              void* d_out, int out_size)
{
    const float* x       = (const float*)d_in[0];
    const int*   mask    = (const int*)  d_in[1];
    const float* lg_old  = (const float*)d_in[2];
    const int*   a_taken = (const int*)  d_in[3];
    const float* GAE     = (const float*)d_in[4];
    const float* old_v   = (const float*)d_in[5];
    const float* rets    = (const float*)d_in[6];
    const float* W1 = (const float*)d_in[7];  const float* b1 = (const float*)d_in[8];
    const float* W2 = (const float*)d_in[9];  const float* b2 = (const float*)d_in[10];
    const float* W3 = (const float*)d_in[11]; const float* b3 = (const float*)d_in[12];
    const float* W4 = (const float*)d_in[13]; const float* b4 = (const float*)d_in[14];
    const float* lstm_k = (const float*)d_in[15];
    const float* lstm_r = (const float*)d_in[16];
    const float* lstm_b = (const float*)d_in[17];
    const float* pir_W  = (const float*)d_in[18];
    const float* pir_b  = (const float*)d_in[19];
    const float* pim_W  = (const float*)d_in[20];
    const float* pim_b  = (const float*)d_in[21];
    const float* v_W    = (const float*)d_in[22];
    const float* v_b    = (const float*)d_in[23];
    float* out = (float*)d_out;

    void *p_feat, *p_gatesx, *p_lstm, *p_pimlog, *p_Asp, *p_Bpim, *p_Bk;
    cudaGetSymbolAddress(&p_feat,   g_feat);
    cudaGetSymbolAddress(&p_gatesx, g_gatesx);
    cudaGetSymbolAddress(&p_lstm,   g_lstm);
    cudaGetSymbolAddress(&p_pimlog, g_pimlog);
    cudaGetSymbolAddress(&p_Asp,    g_Asp);
    cudaGetSymbolAddress(&p_Bpim,   g_Bpim);
    cudaGetSymbolAddress(&p_Bk,     g_Bk);

    cudaFuncSetAttribute(lstm_persist_kernel,
                         cudaFuncAttributeMaxDynamicSharedMemorySize, LSTM_SMEM_BYTES);
    cudaFuncSetAttribute(bf16_gemm_ps_kernel,
                         cudaFuncAttributeMaxDynamicSharedMemorySize, PS_SMEM_BYTES);

    conv_kernel<<<BT, 128>>>(x, W1, b1, W2, b2, W3, b3, W4, b4);
    pack_wr_kernel<<<1024, 256>>>(lstm_r);
    splitB_kernel<<<512, 256>>>(lstm_k, (uint2*)p_Bk, 1024);
    splitB_kernel<<<2048, 256>>>(pim_W, (uint2*)p_Bpim, 4096);
    split_tr4096_kernel<<<2048, 256>>>((const float*)p_feat, (uint2*)p_Asp, 256);

    // gates_x = feat @ lstm_k + lstm_b (4096x1024), transposed epilogue [t][gcol][b]
    bf16_gemm_ps_kernel<<<dim3(8, 32), 256, PS_SMEM_BYTES>>>(
        (const uint2*)p_Asp, (const uint2*)p_Bk, lstm_b, (float*)p_gatesx,
        BT, 1024, 128, 1);

    lstm_persist_kernel<<<NCTA, 512, LSTM_SMEM_BYTES>>>();

    split_tr4096_kernel<<<2048, 256>>>((const float*)p_lstm, (uint2*)p_Asp, 256);

    // pim logits = lstm @ pim_W + pim_b (4096x4096)
    bf16_gemm_ps_kernel<<<dim3(32, 32), 256, PS_SMEM_BYTES>>>(
        (const uint2*)p_Asp, (const uint2*)p_Bpim, pim_b, (float*)p_pimlog,
        BT, 4096, 128, 0);

    pir_kernel<<<BT, 64>>>(pir_W, pir_b, v_W, v_b);
    pim_softmax_kernel<<<BT, 256>>>(mask, a_taken);
    gae_stats_kernel<<<1, 1024>>>(GAE);
    pg_terms_kernel<<<16, 256>>>(lg_old, a_taken, GAE);
    vf_kernel<<<128, 256>>>(old_v, rets);
    finalize_kernel<<<1, 1024>>>(out);
}

// round 16
// speedup vs baseline: 1.6607x; 1.0781x over previous
#include <cuda_runtime.h>
#include <cuda_bf16.h>
#include <math.h>
#include <stdint.h>

#define BT    4096
#define HID   256
#define TSTEP 64
#define BB    64
#define NCTA  128

// ---------------- scratch (static device memory; no allocations) ----------------
__device__ float g_feat  [BT * HID];          // conv features (B*T, 256)
__device__ float g_gatesx[BT * 1024];         // x @ Wk + b, TRANSPOSED: [t][gatecol][b]
__device__ float g_lstm  [BT * HID];          // lstm hidden states
__device__ float g_Wr4   [256 * 1024];        // Wr packed: [k][j][gate] interleaved
__device__ float g_hbuf  [2][16384];          // LSTM h double buffer, [j][b]
__device__ float g_pimlog[16777216];          // pim logits (4096 x 4096)
__device__ uint2 g_Asp   [128 * 4096];        // split activations [kpair][m] (hi-pair, lo-pair)
__device__ uint2 g_Bpim  [128 * 4096];        // split pim_W [kpair][n]
__device__ uint2 g_Bk    [128 * 1024];        // split lstm_k [kpair][n]
__device__ float g_pir   [BT * 36];           // pir probabilities
__device__ float g_entpir[BT];
__device__ float g_entpim[BT];
__device__ float g_ppim  [BT];                // pim prob of taken action
__device__ float g_vpred [BT];
__device__ float g_pgvals[BT];
__device__ float g_vfvals[BT];
__device__ float g_stats [2];                 // gae mean, std
__device__ unsigned g_bar_cnt = 0;            // grid barrier arrive counter
__device__ unsigned g_bar_phase = 0;          // grid barrier phase flag

__device__ __forceinline__ float leaky(float v) { return v > 0.f ? v : 0.2f * v; }
__device__ __forceinline__ float sigmoidf(float v) { return 1.f / (1.f + expf(-v)); }

__device__ __forceinline__ uint32_t smem_u32(const void* p)
{
    uint32_t a;
    asm("{ .reg .u64 t; cvta.to.shared.u64 t, %1; cvt.u32.u64 %0, t; }" : "=r"(a) : "l"(p));
    return a;
}

__device__ __forceinline__ void cp_async16(uint32_t dst, const void* src)
{
    asm volatile("cp.async.cg.shared.global [%0], [%1], 16;" :: "r"(dst), "l"(src));
}

// ---------------- fused conv stack: one block per image ----------------
__global__ __launch_bounds__(128) void conv_kernel(
    const float* __restrict__ x,
    const float* __restrict__ W1, const float* __restrict__ b1,
    const float* __restrict__ W2, const float* __restrict__ b2,
    const float* __restrict__ W3, const float* __restrict__ b3,
    const float* __restrict__ W4, const float* __restrict__ b4)
{
    __shared__ float sx[832];   // 13*8*8
    __shared__ float h1[384];   // 6*4*16
    __shared__ float h2[480];   // 5*3*32
    __shared__ float h3[128];   // 2*1*64
    const int img = blockIdx.x;
    const float* xin = x + img * 832;
    for (int i = threadIdx.x; i < 832; i += blockDim.x) sx[i] = xin[i];
    __syncthreads();

    // conv1: (13,8,8) -> (6,4,16), k=2 s=2
    for (int idx = threadIdx.x; idx < 384; idx += blockDim.x) {
        int oc = idx & 15, sp = idx >> 4;
        int ow = sp & 3, oh = sp >> 2;
        float v = b1[oc];
        #pragma unroll
        for (int kh = 0; kh < 2; kh++)
        #pragma unroll
        for (int kw = 0; kw < 2; kw++) {
            const float* xp = &sx[((oh * 2 + kh) * 8 + (ow * 2 + kw)) * 8];
            const float* wp = &W1[((kh * 2 + kw) * 8) * 16 + oc];
            #pragma unroll
            for (int ic = 0; ic < 8; ic++) v += xp[ic] * wp[ic * 16];
        }
        h1[idx] = leaky(v);
    }
    __syncthreads();

    // conv2: (6,4,16) -> (5,3,32), k=2 s=1
    for (int idx = threadIdx.x; idx < 480; idx += blockDim.x) {
        int oc = idx & 31, sp = idx >> 5;
        int ow = sp % 3, oh = sp / 3;
        float v = b2[oc];
        #pragma unroll
        for (int kh = 0; kh < 2; kh++)
        #pragma unroll
        for (int kw = 0; kw < 2; kw++) {
            const float* hp = &h1[((oh + kh) * 4 + (ow + kw)) * 16];
            const float* wp = &W2[((kh * 2 + kw) * 16) * 32 + oc];
            #pragma unroll
            for (int ic = 0; ic < 16; ic++) v += hp[ic] * wp[ic * 32];
        }
        h2[idx] = leaky(v);
    }
    __syncthreads();

    // conv3: (5,3,32) -> (2,1,64), k=2 s=2
    for (int idx = threadIdx.x; idx < 128; idx += blockDim.x) {
        int oc = idx & 63, oh = idx >> 6;
        float v = b3[oc];
        #pragma unroll
        for (int kh = 0; kh < 2; kh++)
        #pragma unroll
        for (int kw = 0; kw < 2; kw++) {
            const float* hp = &h2[((oh * 2 + kh) * 3 + kw) * 32];
            const float* wp = &W3[((kh * 2 + kw) * 32) * 64 + oc];
            #pragma unroll
            for (int ic = 0; ic < 32; ic++) v += hp[ic] * wp[ic * 64];
        }
        h3[idx] = leaky(v);
    }
    __syncthreads();

    // conv4 1x1: (2,1,64)->(2,1,128) + channels_first flatten: feat[2*oc+oh]
    for (int idx = threadIdx.x; idx < 256; idx += blockDim.x) {
        int oc = idx >> 1, oh = idx & 1;
        float v = b4[oc];
        #pragma unroll
        for (int ic = 0; ic < 64; ic++) v += h3[oh * 64 + ic] * W4[ic * 128 + oc];
        g_feat[img * 256 + idx] = leaky(v);
    }
}

// ---------------- bf16 hi/lo split helpers ----------------
__device__ __forceinline__ uint2 split_bf16pair(float a0, float a1)
{
    __nv_bfloat16 h0 = __float2bfloat16(a0);
    __nv_bfloat16 h1 = __float2bfloat16(a1);
    float r0 = a0 - __bfloat162float(h0);
    float r1 = a1 - __bfloat162float(h1);
    __nv_bfloat162 hp = __halves2bfloat162(h0, h1);
    __nv_bfloat162 lp = __halves2bfloat162(__float2bfloat16(r0), __float2bfloat16(r1));
    uint2 r;
    r.x = *(const uint32_t*)&hp;
    r.y = *(const uint32_t*)&lp;
    return r;
}

// split + transpose: src [4096][K] f32 -> dst [K/2][4096] uint2
__global__ __launch_bounds__(256) void split_tr4096_kernel(const float* __restrict__ src,
                                                           uint2* __restrict__ dst, int K)
{
    int idx = blockIdx.x * 256 + threadIdx.x;
    int kp = idx >> 12, m = idx & 4095;
    float2 a = *(const float2*)&src[(size_t)m * K + 2 * kp];
    dst[idx] = split_bf16pair(a.x, a.y);
}

// split B [K][N] f32 -> [K/2][N] uint2
__global__ __launch_bounds__(256) void splitB_kernel(const float* __restrict__ src,
                                                     uint2* __restrict__ dst, int N)
{
    int idx = blockIdx.x * 256 + threadIdx.x;
    int kp = idx / N, n = idx - kp * N;
    float a0 = src[(size_t)(2 * kp) * N + n];
    float a1 = src[(size_t)(2 * kp + 1) * N + n];
    dst[idx] = split_bf16pair(a0, a1);
}

// ---------------- 3xBF16 tensor GEMM (m16n8k16), pre-split inputs, cp.async ----------
#define MMA_BF16(d, a, b0v, b1v) \
    asm volatile("mma.sync.aligned.m16n8k16.row.col.f32.bf16.bf16.f32 " \
        "{%0,%1,%2,%3}, {%4,%5,%6,%7}, {%8,%9}, {%0,%1,%2,%3};" \
        : "+f"((d)[0]), "+f"((d)[1]), "+f"((d)[2]), "+f"((d)[3]) \
        : "r"((a)[0]), "r"((a)[1]), "r"((a)[2]), "r"((a)[3]), "r"(b0v), "r"(b1v))

#define PS_TILE  1056                 // 8 kpair rows * 132 uint2
#define PS_SMEM_BYTES (4 * PS_TILE * 8)

__device__ __forceinline__ void load_tiles_ps(uint2* Asb, uint2* Bsb,
    const uint2* __restrict__ A, const uint2* __restrict__ B,
    int M, int N, int m0, int n0, int kp0, int tid)
{
    #pragma unroll
    for (int i = 0; i < 2; i++) {
        int r  = (tid >> 6) + (i << 2);
        int cc = (tid & 63) << 1;
        cp_async16(smem_u32(Asb + r * 132 + cc), A + (size_t)(kp0 + r) * M + m0 + cc);
        cp_async16(smem_u32(Bsb + r * 132 + cc), B + (size_t)(kp0 + r) * N + n0 + cc);
    }
}

__global__ __launch_bounds__(256) void bf16_gemm_ps_kernel(
    const uint2* __restrict__ A, const uint2* __restrict__ B,
    const float* __restrict__ bias, float* __restrict__ C,
    int M, int N, int K2, int trans_out)
{
    extern __shared__ uint2 ps[];
    uint2* As0 = ps;
    uint2* Bs0 = ps + 2 * PS_TILE;
    const int tid  = threadIdx.x;
    const int lane = tid & 31, warp = tid >> 5;
    const int wm = warp & 3, wn = warp >> 2;
    const int g = lane >> 2, tg = lane & 3;
    const int m0 = blockIdx.y * 128, n0 = blockIdx.x * 128;

    float acc[2][8][4];
    #pragma unroll
    for (int a = 0; a < 2; a++)
        #pragma unroll
        for (int b = 0; b < 8; b++)
            #pragma unroll
            for (int c = 0; c < 4; c++) acc[a][b][c] = 0.f;

    load_tiles_ps(As0, Bs0, A, B, M, N, m0, n0, 0, tid);
    asm volatile("cp.async.commit_group;" ::: "memory");

    int st = 0;
    for (int kp0 = 0; kp0 < K2; kp0 += 8) {
        if (kp0 + 8 < K2) {
            load_tiles_ps(As0 + (st ^ 1) * PS_TILE, Bs0 + (st ^ 1) * PS_TILE,
                          A, B, M, N, m0, n0, kp0 + 8, tid);
            asm volatile("cp.async.commit_group;" ::: "memory");
            asm volatile("cp.async.wait_group 1;" ::: "memory");
        } else {
            asm volatile("cp.async.wait_group 0;" ::: "memory");
        }
        __syncthreads();

        const uint2* Ac = As0 + st * PS_TILE;
        const uint2* Bc = Bs0 + st * PS_TILE;

        uint32_t ah[2][4], al[2][4];
        #pragma unroll
        for (int mt = 0; mt < 2; mt++) {
            const int rb = wm * 32 + mt * 16;
            uint2 x0 = Ac[tg * 132 + rb + g];
            uint2 x1 = Ac[tg * 132 + rb + g + 8];
            uint2 x2 = Ac[(tg + 4) * 132 + rb + g];
            uint2 x3 = Ac[(tg + 4) * 132 + rb + g + 8];
            ah[mt][0] = x0.x; al[mt][0] = x0.y;
            ah[mt][1] = x1.x; al[mt][1] = x1.y;
            ah[mt][2] = x2.x; al[mt][2] = x2.y;
            ah[mt][3] = x3.x; al[mt][3] = x3.y;
        }
        #pragma unroll
        for (int nt = 0; nt < 8; nt++) {
            const int nb = wn * 64 + nt * 8 + g;
            uint2 y0 = Bc[tg * 132 + nb];
            uint2 y1 = Bc[(tg + 4) * 132 + nb];
            #pragma unroll
            for (int mt = 0; mt < 2; mt++) {
                MMA_BF16(acc[mt][nt], ah[mt], y0.x, y1.x);  // hi*hi
                MMA_BF16(acc[mt][nt], al[mt], y0.x, y1.x);  // lo*hi
                MMA_BF16(acc[mt][nt], ah[mt], y0.y, y1.y);  // hi*lo
            }
        }
        __syncthreads();
        st ^= 1;
    }

    #pragma unroll
    for (int mt = 0; mt < 2; mt++) {
        const int r0 = m0 + wm * 32 + mt * 16 + g;
        #pragma unroll
        for (int nt = 0; nt < 8; nt++) {
            const int col = n0 + wn * 64 + nt * 8 + 2 * tg;
            const float b0v = bias[col], b1v = bias[col + 1];
            if (!trans_out) {
                *(float2*)&C[(size_t)r0 * N + col] =
                    make_float2(acc[mt][nt][0] + b0v, acc[mt][nt][1] + b1v);
                *(float2*)&C[(size_t)(r0 + 8) * N + col] =
                    make_float2(acc[mt][nt][2] + b0v, acc[mt][nt][3] + b1v);
            } else {
                int t0 = r0 & 63, bb0 = r0 >> 6;
                int t1 = (r0 + 8) & 63, bb1 = (r0 + 8) >> 6;
                C[((size_t)t0 << 16) + ((size_t)col << 6) + bb0]       = acc[mt][nt][0] + b0v;
                C[((size_t)t0 << 16) + ((size_t)(col + 1) << 6) + bb0] = acc[mt][nt][1] + b1v;
                C[((size_t)t1 << 16) + ((size_t)col << 6) + bb1]       = acc[mt][nt][2] + b0v;
                C[((size_t)t1 << 16) + ((size_t)(col + 1) << 6) + bb1] = acc[mt][nt][3] + b1v;
            }
        }
    }
}

// ---------------- pack Wr: Wr[k*1024 + g*256 + j] -> g_Wr4[k*1024 + j*4 + g] ----------------
__global__ __launch_bounds__(256) void pack_wr_kernel(const float* __restrict__ Wr)
{
    int idx = blockIdx.x * 256 + threadIdx.x;
    int k = idx >> 10, col = idx & 1023;
    int g = col >> 8, j = col & 255;
    g_Wr4[(k << 10) + (j << 2) + g] = Wr[idx];
}

// ---------------- LSTM: persistent full-chip kernel, release/acquire grid barrier ----------
#define LSTM_SMEM_BYTES ((2048 + 16384 + 4096) * 4)

__device__ __forceinline__ void grid_barrier(unsigned target)
{
    __syncthreads();
    if (threadIdx.x == 0) {
        unsigned v;
        asm volatile("atom.add.release.gpu.u32 %0, [%1], 1;"
                     : "=r"(v) : "l"(&g_bar_cnt) : "memory");
        if (v == NCTA - 1) {
            g_bar_cnt = 0;
            asm volatile("st.release.gpu.u32 [%0], %1;"
                         :: "l"(&g_bar_phase), "r"(target) : "memory");
        } else {
            unsigned p;
            do {
                asm volatile("ld.acquire.gpu.u32 %0, [%1];"
                             : "=r"(p) : "l"(&g_bar_phase) : "memory");
            } while (p < target);
        }
    }
    __syncthreads();
}

__global__ __launch_bounds__(512) void lstm_persist_kernel()
{
    extern __shared__ float smem[];
    float*  sw  = smem;                       // [k*8 + c] weight slice, 2048 floats
    float*  sh  = smem + 2048;                // h tile [k*64 + b], 16384 floats
    float4* sp4 = (float4*)(smem + 2048 + 16384); // partials

    const int tid = threadIdx.x;
    const int row = tid & 63;
    const int oct = tid >> 6;
    const int jbase = blockIdx.x << 1;

    const float* wsrc = g_Wr4 + (jbase << 2);
    for (int i = tid; i < 2048; i += 512) {
        int k = i >> 3, c = i & 7;
        sw[i] = wsrc[(k << 10) + c];
    }
    if (tid < 128) g_hbuf[0][(jbase << 6) + tid] = 0.f;

    const int js = tid >> 6;
    const int jg = jbase + js;
    float c_state = 0.f;

    grid_barrier(1);

    for (int t = 0; t < TSTEP; t++) {
        float gx0, gx1, gx2, gx3;
        if (tid < 128) {
            const float* gp = g_gatesx + ((size_t)t << 16) + ((size_t)jg << 6) + row;
            gx0 = gp[0];
            gx1 = gp[256 * 64];
            gx2 = gp[512 * 64];
            gx3 = gp[768 * 64];
        }
        {
            const float4* hb = (const float4*)g_hbuf[t & 1];
            float4* sh4 = (float4*)sh;
            #pragma unroll
            for (int i = 0; i < 8; i++)
                sh4[tid + (i << 9)] = __ldcg(&hb[tid + (i << 9)]);
        }
        __syncthreads();

        float4 a0 = make_float4(0.f, 0.f, 0.f, 0.f);
        float4 a1 = make_float4(0.f, 0.f, 0.f, 0.f);
        const int k0 = oct << 5;
        #pragma unroll 8
        for (int kk = 0; kk < 32; kk++) {
            const int k = k0 + kk;
            float4 w0 = *(const float4*)&sw[k << 3];
            float4 w1 = *(const float4*)&sw[(k << 3) + 4];
            float hv = sh[(k << 6) + row];
            a0.x += w0.x * hv; a0.y += w0.y * hv; a0.z += w0.z * hv; a0.w += w0.w * hv;
            a1.x += w1.x * hv; a1.y += w1.y * hv; a1.z += w1.z * hv; a1.w += w1.w * hv;
        }
        sp4[(oct << 7) + row]      = a0;
        sp4[(oct << 7) + 64 + row] = a1;
        __syncthreads();

        if (tid < 128) {
            float zi = gx0, zf = gx1, zg = gx2, zo = gx3;
            #pragma unroll
            for (int o = 0; o < 8; o++) {
                float4 z = sp4[(o << 7) + (js << 6) + row];
                zi += z.x; zf += z.y; zg += z.z; zo += z.w;
            }
            c_state = sigmoidf(zf) * c_state + sigmoidf(zi) * tanhf(zg);
            float hn = sigmoidf(zo) * tanhf(c_state);
            g_lstm[(((size_t)row * TSTEP + t) << 8) + jg] = hn;
            g_hbuf[(t + 1) & 1][(jg << 6) + row] = hn;
        }
        grid_barrier(t + 2);
    }

    // reset barrier state for the next graph replay
    if (tid == 0) {
        unsigned v;
        asm volatile("atom.add.release.gpu.u32 %0, [%1], 1;"
                     : "=r"(v) : "l"(&g_bar_cnt) : "memory");
        if (v == NCTA - 1) {
            g_bar_cnt = 0;
            asm volatile("st.release.gpu.u32 [%0], %1;"
                         :: "l"(&g_bar_phase), "r"(0u) : "memory");
        }
    }
}

// ---------------- pir head + value head fused (one block per row, 64 threads) --------
__global__ __launch_bounds__(64) void pir_kernel(const float* __restrict__ pir_W,
                                                 const float* __restrict__ pir_b,
                                                 const float* __restrict__ v_W,
                                                 const float* __restrict__ v_b)
{
    __shared__ float sh[256];
    __shared__ float lg[36];
    __shared__ float red[64];
    __shared__ float s_mx, s_sum;
    const int row = blockIdx.x;
    const int tid = threadIdx.x;
    for (int i = tid; i < 256; i += 64) sh[i] = g_lstm[(size_t)row * 256 + i];
    __syncthreads();

    float vp = 0.f;
    #pragma unroll
    for (int k = tid; k < 256; k += 64) vp += sh[k] * v_W[k];

    if (tid < 36) {
        float v = pir_b[tid];
        for (int k = 0; k < 256; k++) v += sh[k] * pir_W[k * 36 + tid];
        lg[tid] = v;
    }

    red[tid] = vp; __syncthreads();
    for (int s = 32; s > 0; s >>= 1) { if (tid < s) red[tid] += red[tid + s]; __syncthreads(); }
    if (tid == 0) g_vpred[row] = red[0] + v_b[0];
    __syncthreads();

    red[tid] = (tid < 36) ? lg[tid] : -1e30f; __syncthreads();
    for (int s = 32; s > 0; s >>= 1) { if (tid < s) red[tid] = fmaxf(red[tid], red[tid + s]); __syncthreads(); }
    if (tid == 0) s_mx = red[0];
    __syncthreads();

    float e = 0.f;
    if (tid < 36) e = expf(lg[tid] - s_mx);
    red[tid] = e; __syncthreads();
    for (int s = 32; s > 0; s >>= 1) { if (tid < s) red[tid] += red[tid + s]; __syncthreads(); }
    if (tid == 0) s_sum = red[0];
    __syncthreads();

    float ent = 0.f;
    if (tid < 36) {
        float p = e / s_sum;
        g_pir[row * 36 + tid] = p;
        ent = p * logf(p);
    }
    red[tid] = ent; __syncthreads();
    for (int s = 32; s > 0; s >>= 1) { if (tid < s) red[tid] += red[tid + s]; __syncthreads(); }
    if (tid == 0) g_entpir[row] = red[0];
}

// ---------------- pim softmax: smem row cache, logf-free entropy ----------------
// ent = S3/D - ln(D) * S2/D,  S3 = sum_masked q*(lg-mx), S2 = sum_masked q, D = denom
__global__ __launch_bounds__(256) void pim_softmax_kernel(const int* __restrict__ mask,
                                                          const int* __restrict__ a_taken)
{
    __shared__ float sq[4096];               // caches logits (NOT exp)
    __shared__ unsigned char sm8[4096];
    __shared__ float red[256];
    __shared__ float s_mx, s_S, s_SM, s_S3;
    const int row = blockIdx.x;
    const int tid = threadIdx.x;
    const float4* __restrict__ lg4 = (const float4*)(g_pimlog + ((size_t)row << 12));
    const int4*   __restrict__ m4  = (const int4*)(mask + ((size_t)row << 12));

    float mx = -1e30f;
    for (int i = tid; i < 1024; i += 256) {
        float4 v = lg4[i];
        int4 m = m4[i];
        *(float4*)&sq[i << 2] = v;
        sm8[(i << 2) + 0] = (unsigned char)m.x;
        sm8[(i << 2) + 1] = (unsigned char)m.y;
        sm8[(i << 2) + 2] = (unsigned char)m.z;
        sm8[(i << 2) + 3] = (unsigned char)m.w;
        mx = fmaxf(mx, fmaxf(fmaxf(v.x, v.y), fmaxf(v.z, v.w)));
    }
    red[tid] = mx; __syncthreads();
    for (int s = 128; s > 0; s >>= 1) { if (tid < s) red[tid] = fmaxf(red[tid], red[tid + s]); __syncthreads(); }
    if (tid == 0) s_mx = red[0];
    __syncthreads();
    mx = s_mx;

    // one pass: total sum, masked sum, masked q*(lg-mx) sum
    float ssum = 0.f, smsum = 0.f, s3 = 0.f;
    for (int i = tid; i < 4096; i += 256) {
        float d = sq[i] - mx;
        float qv = expf(d);
        ssum += qv;
        if (sm8[i]) { smsum += qv; s3 += qv * d; }
    }
    __syncthreads();
    red[tid] = ssum; __syncthreads();
    for (int s = 128; s > 0; s >>= 1) { if (tid < s) red[tid] += red[tid + s]; __syncthreads(); }
    if (tid == 0) s_S = red[0];
    __syncthreads();
    red[tid] = smsum; __syncthreads();
    for (int s = 128; s > 0; s >>= 1) { if (tid < s) red[tid] += red[tid + s]; __syncthreads(); }
    if (tid == 0) s_SM = red[0];
    __syncthreads();
    red[tid] = s3; __syncthreads();
    for (int s = 128; s > 0; s >>= 1) { if (tid < s) red[tid] += red[tid + s]; __syncthreads(); }
    if (tid == 0) s_S3 = red[0];
    __syncthreads();

    if (tid == 0) {
        const float D = (s_SM > 0.f) ? s_SM : s_S;
        g_entpim[row] = (s_S3 - logf(D) * s_SM) / D;
        int a = a_taken[row];
        g_ppim[row] = sm8[a] ? expf(sq[a] - mx) / D : 0.f;
    }
}

// ---------------- block-wide double sum (blockDim must be 1024) ----------------
__device__ double block_sum_d(double v)
{
    __shared__ double rd[1024];
    const int tid = threadIdx.x;
    __syncthreads();
    rd[tid] = v; __syncthreads();
    for (int s = 512; s > 0; s >>= 1) { if (tid < s) rd[tid] += rd[tid + s]; __syncthreads(); }
    double r = rd[0];
    __syncthreads();
    return r;
}

__global__ __launch_bounds__(1024) void gae_stats_kernel(const float* __restrict__ GAE)
{
    const int tid = threadIdx.x;
    double s = 0.0;
    for (int i = tid; i < BT; i += 1024) s += (double)GAE[i];
    double tot = block_sum_d(s);
    double mean = tot / (double)BT;
    double v = 0.0;
    for (int i = tid; i < BT; i += 1024) { double d = (double)GAE[i] - mean; v += d * d; }
    double var = block_sum_d(v) / (double)BT;
    if (tid == 0) { g_stats[0] = (float)mean; g_stats[1] = (float)sqrt(var); }
}

__global__ void pg_terms_kernel(const float* __restrict__ lg_old,
                                const int* __restrict__ a_taken,
                                const float* __restrict__ GAE)
{
    const int i = blockIdx.x * blockDim.x + threadIdx.x;
    if (i >= BT) return;
    const float mean = g_stats[0], std = g_stats[1];
    float g = (GAE[i] - mean) / (std + 1e-8f);
    int a = a_taken[i];
    float p = ((i & 1) == 0) ? g_pir[i * 36 + a] : g_ppim[i];
    float lgn = logf(p);
    float rt = expf(lgn - lg_old[i]);
    float rtc = fminf(fmaxf(rt, 0.8f), 1.2f);
    g_pgvals[i] = fmaxf(-g * rt, -g * rtc);
}

// vf broadcast loss: 128 blocks x 32 rows, ret/old_v cached in smem, warp-per-row
__global__ __launch_bounds__(256) void vf_kernel(const float* __restrict__ old_v,
                                                 const float* __restrict__ ret)
{
    __shared__ float sret[BT];
    __shared__ float sov[BT];
    const int tid = threadIdx.x;
    for (int j = tid; j < BT; j += 256) { sret[j] = ret[j]; sov[j] = old_v[j]; }
    __syncthreads();
    const int warp = tid >> 5, lane = tid & 31;
    #pragma unroll
    for (int ii = 0; ii < 4; ii++) {
        const int i = blockIdx.x * 32 + ii * 8 + warp;
        const float vp = g_vpred[i];
        float s = 0.f;
        for (int j = lane; j < BT; j += 32) {
            float r = sret[j];
            float ov = sov[j];
            float d1 = vp - r;
            float dc = fminf(fmaxf(vp - ov, -0.2f), 0.2f);
            float d2 = ov + dc - r;
            s += fmaxf(d1 * d1, d2 * d2);
        }
        #pragma unroll
        for (int o = 16; o > 0; o >>= 1) s += __shfl_down_sync(0xffffffffu, s, o);
        if (lane == 0) g_vfvals[i] = s;
    }
}

__global__ __launch_bounds__(1024) void finalize_kernel(float* __restrict__ out)
{
    const int tid = threadIdx.x;
    double s = 0.0;
    for (int i = tid; i < BT; i += 1024) s += (double)g_pgvals[i];
    double pg = block_sum_d(s) / (double)BT;

    s = 0.0;
    for (int i = tid; i < BT; i += 1024) s += (double)g_entpir[i] + (double)g_entpim[i];
    double entropy = -block_sum_d(s);

    s = 0.0;
    for (int i = tid; i < BT; i += 1024) s += (double)g_vfvals[i];
    double vf = 0.5 * block_sum_d(s) / ((double)BT * (double)BT);

    if (tid == 0) {
        out[0] = (float)(pg - entropy + vf);
        out[1] = (float)pg;
        out[2] = (float)entropy;
        out[3] = (float)vf;
    }
}

// ---------------- launcher (fork/join streams, graph-capturable) ----------------
extern "C" void kernel_launch(void* const* d_in, const int* in_sizes, int n_in,
                              void* d_out, int out_size)
{
    const float* x       = (const float*)d_in[0];
    const int*   mask    = (const int*)  d_in[1];
    const float* lg_old  = (const float*)d_in[2];
    const int*   a_taken = (const int*)  d_in[3];
    const float* GAE     = (const float*)d_in[4];
    const float* old_v   = (const float*)d_in[5];
    const float* rets    = (const float*)d_in[6];
    const float* W1 = (const float*)d_in[7];  const float* b1 = (const float*)d_in[8];
    const float* W2 = (const float*)d_in[9];  const float* b2 = (const float*)d_in[10];
    const float* W3 = (const float*)d_in[11]; const float* b3 = (const float*)d_in[12];
    const float* W4 = (const float*)d_in[13]; const float* b4 = (const float*)d_in[14];
    const float* lstm_k = (const float*)d_in[15];
    const float* lstm_r = (const float*)d_in[16];
    const float* lstm_b = (const float*)d_in[17];
    const float* pir_W  = (const float*)d_in[18];
    const float* pir_b  = (const float*)d_in[19];
    const float* pim_W  = (const float*)d_in[20];
    const float* pim_b  = (const float*)d_in[21];
    const float* v_W    = (const float*)d_in[22];
    const float* v_b    = (const float*)d_in[23];
    float* out = (float*)d_out;

    void *p_feat, *p_gatesx, *p_lstm, *p_pimlog, *p_Asp, *p_Bpim, *p_Bk;
    cudaGetSymbolAddress(&p_feat,   g_feat);
    cudaGetSymbolAddress(&p_gatesx, g_gatesx);
    cudaGetSymbolAddress(&p_lstm,   g_lstm);
    cudaGetSymbolAddress(&p_pimlog, g_pimlog);
    cudaGetSymbolAddress(&p_Asp,    g_Asp);
    cudaGetSymbolAddress(&p_Bpim,   g_Bpim);
    cudaGetSymbolAddress(&p_Bk,     g_Bk);

    cudaFuncSetAttribute(lstm_persist_kernel,
                         cudaFuncAttributeMaxDynamicSharedMemorySize, LSTM_SMEM_BYTES);
    cudaFuncSetAttribute(bf16_gemm_ps_kernel,
                         cudaFuncAttributeMaxDynamicSharedMemorySize, PS_SMEM_BYTES);

    // one-time stream/event setup (first call is the uncaptured correctness run)
    static cudaStream_t s2 = nullptr;
    static cudaEvent_t eFork, eAux, eLstm, eJoin;
    if (!s2) {
        cudaStreamCreateWithFlags(&s2, cudaStreamNonBlocking);
        cudaEventCreateWithFlags(&eFork, cudaEventDisableTiming);
        cudaEventCreateWithFlags(&eAux,  cudaEventDisableTiming);
        cudaEventCreateWithFlags(&eLstm, cudaEventDisableTiming);
        cudaEventCreateWithFlags(&eJoin, cudaEventDisableTiming);
    }

    // fork
    cudaEventRecord(eFork, 0);
    cudaStreamWaitEvent(s2, eFork, 0);

    // side stream: input-only prep
    gae_stats_kernel<<<1, 1024, 0, s2>>>(GAE);
    pack_wr_kernel<<<1024, 256, 0, s2>>>(lstm_r);
    splitB_kernel<<<512, 256, 0, s2>>>(lstm_k, (uint2*)p_Bk, 1024);
    splitB_kernel<<<2048, 256, 0, s2>>>(pim_W, (uint2*)p_Bpim, 4096);
    cudaEventRecord(eAux, s2);

    // main stream: conv + activation split (independent of side work)
    conv_kernel<<<BT, 128>>>(x, W1, b1, W2, b2, W3, b3, W4, b4);
    split_tr4096_kernel<<<2048, 256>>>((const float*)p_feat, (uint2*)p_Asp, 256);

    // gatesx needs g_Bk; lstm needs g_Wr4
    cudaStreamWaitEvent(0, eAux, 0);
    bf16_gemm_ps_kernel<<<dim3(8, 32), 256, PS_SMEM_BYTES>>>(
        (const uint2*)p_Asp, (const uint2*)p_Bk, lstm_b, (float*)p_gatesx,
        BT, 1024, 128, 1);

    lstm_persist_kernel<<<NCTA, 512, LSTM_SMEM_BYTES>>>();
    cudaEventRecord(eLstm, 0);

    // side stream: pir+vpred then vf (reads g_lstm / g_vpred only)
    cudaStreamWaitEvent(s2, eLstm, 0);
    pir_kernel<<<BT, 64, 0, s2>>>(pir_W, pir_b, v_W, v_b);
    vf_kernel<<<128, 256, 0, s2>>>(old_v, rets);
    cudaEventRecord(eJoin, s2);

    // main stream: pim logits + softmax
    split_tr4096_kernel<<<2048, 256>>>((const float*)p_lstm, (uint2*)p_Asp, 256);
    bf16_gemm_ps_kernel<<<dim3(32, 32), 256, PS_SMEM_BYTES>>>(
        (const uint2*)p_Asp, (const uint2*)p_Bpim, pim_b, (float*)p_pimlog,
        BT, 4096, 128, 0);
    pim_softmax_kernel<<<BT, 256>>>(mask, a_taken);

    // join, then losses
    cudaStreamWaitEvent(0, eJoin, 0);
    pg_terms_kernel<<<16, 256>>>(lg_old, a_taken, GAE);
    finalize_kernel<<<1, 1024>>>(out);
}